// round 8
// baseline (speedup 1.0000x reference)
#include <cuda_runtime.h>
#include <math.h>
#include <stdint.h>

// Problem dims
#define Bb   256
#define Ss   512
#define Hh   256
#define OUTD 3
#define NST  64
#define INW  259
#define G4   (4*Hh)
#define NSL  2
#define SLROWS (Ss/NSL)      // 256
#define GRID 512
#define NTHR 256

// Output layout
#define OFF_PRED 0
#define OFF_HID  (Bb*NST*OUTD)          // 49152
#define OFF_ATT  (OFF_HID + Bb*Hh)      // 114688

// Persistent device state
__device__ float g_hbuf[2][Bb*Hh];  // ping-pong h
__device__ float g_c[Bb*Hh];
__device__ float g_x[Bb*OUTD];
__device__ float g_v[Bb*Hh];
__device__ float g_WcatT[512*G4];   // [k][n]
__device__ float g_Wx[G4*OUTD];
__device__ float g_bias[G4];
__device__ float g_M[Hh*Hh];        // [k][j]
__device__ float g_vb[Hh];
__device__ float g_pm[Bb*NSL];
__device__ float g_pl[Bb*NSL];
__device__ float g_pctx[Bb*NSL*Hh];
// grid barrier
__device__ unsigned g_cnt;
__device__ unsigned g_gen;

__device__ __forceinline__ float warp_sum(float v){
  #pragma unroll
  for (int o = 16; o; o >>= 1) v += __shfl_xor_sync(0xffffffffu, v, o);
  return v;
}
__device__ __forceinline__ float sigmoidf_(float x){ return 1.f/(1.f+expf(-x)); }

__device__ __forceinline__ uint32_t smem_u32(const void* p){
  return (uint32_t)__cvta_generic_to_shared(p);
}
__device__ __forceinline__ void cp16(uint32_t dst, const void* src){
  asm volatile("cp.async.cg.shared.global [%0], [%1], 16;" :: "r"(dst), "l"(src));
}
#define CP_COMMIT() asm volatile("cp.async.commit_group;")
#define CP_WAIT(n)  asm volatile("cp.async.wait_group %0;" :: "n"(n))

__device__ __forceinline__ void fma2(unsigned long long &d, unsigned long long a, unsigned long long b){
  asm("fma.rn.f32x2 %0, %1, %2, %3;" : "=l"(d) : "l"(a), "l"(b), "l"(d));
}
__device__ __forceinline__ unsigned long long dup2(float v){
  unsigned long long r; uint32_t u = __float_as_uint(v);
  asm("mov.b64 %0, {%1, %1};" : "=l"(r) : "r"(u));
  return r;
}
__device__ __forceinline__ float2 unpack2(unsigned long long v){
  uint32_t lo, hi;
  asm("mov.b64 {%0, %1}, %2;" : "=r"(lo), "=r"(hi) : "l"(v));
  return make_float2(__uint_as_float(lo), __uint_as_float(hi));
}

// grid-wide barrier (all GRID blocks co-resident by construction)
__device__ __forceinline__ void gbar(){
  __threadfence();
  __syncthreads();
  if (threadIdx.x == 0){
    unsigned gen = *(volatile unsigned*)&g_gen;
    if (atomicAdd(&g_cnt, 1u) == GRID-1){
      g_cnt = 0;
      __threadfence();
      atomicAdd(&g_gen, 1u);
    } else {
      while (*(volatile unsigned*)&g_gen == gen) __nanosleep(64);
    }
    __threadfence();
  }
  __syncthreads();
}

// ---------------------------------------------------------------- prep kernels
__global__ void k_init(const float* __restrict__ eh, const float* __restrict__ ec){
  int i = blockIdx.x*blockDim.x + threadIdx.x;
  if (i < Bb*Hh){ g_hbuf[0][i] = eh[i]; g_c[i] = ec[i]; }
  if (i < Bb*OUTD) g_x[i] = 0.f;
  if (i == 0){ g_cnt = 0; g_gen = 0; }
}

__global__ void k_pack(const float* __restrict__ Wih, const float* __restrict__ Whh,
                       const float* __restrict__ bih, const float* __restrict__ bhh){
  int j = blockIdx.x, k = threadIdx.x;
  float val = (k < Hh) ? Wih[j*INW + OUTD + k] : Whh[j*Hh + (k - Hh)];
  g_WcatT[(size_t)k*G4 + j] = val;
  if (k < OUTD) g_Wx[j*OUTD + k] = Wih[j*INW + k];
  if (k == 0)   g_bias[j] = bih[j] + bhh[j];
}

__global__ void k_prep(const float* __restrict__ Wa, const float* __restrict__ ba,
                       const float* __restrict__ Ua){
  int kk = blockIdx.x, j = threadIdx.x;
  float a = 0.f;
  if (kk < Hh){
    #pragma unroll 4
    for (int g = 0; g < Hh; g++) a = fmaf(Wa[g*Hh + kk], Ua[g*Hh + j], a);
    g_M[kk*Hh + j] = a;
  } else {
    #pragma unroll 4
    for (int g = 0; g < Hh; g++) a = fmaf(ba[g], Ua[g*Hh + j], a);
    g_vb[j] = a;
  }
}

// ---------------------------------------------------------------- phase bodies
// Attention: block p -> b = p>>1, slice = p&1 (256 rows, 16 tiles of 16).
__device__ __forceinline__ void attn_phase(
    float* sm, float* v_s, float* ctx_s, float* wbuf, float* tsc, float* tmaxs, float* red0,
    const float* __restrict__ enc, float* __restrict__ out, int t)
{
  int p = blockIdx.x, tid = threadIdx.x, wid = tid >> 5, lane = tid & 31;
  int b = p >> 1, slice = p & 1;
  int s0 = slice * SLROWS;
  const float* encb = enc + (size_t)b*Ss*Hh;

  auto issue = [&](int ti){
    const float4* src = (const float4*)(encb + (size_t)(s0 + ti*16)*Hh);
    uint32_t dst = smem_u32(sm + (ti & 1)*4096);
    #pragma unroll
    for (int i = 0; i < 4; i++){
      int idx = tid + 256*i;
      cp16(dst + idx*16, src + idx);
    }
    CP_COMMIT();
  };

  issue(0);
  v_s[tid] = g_v[b*Hh + tid];
  ctx_s[tid] = 0.f;
  float m_run = -3.0e38f, l_run = 0.f;
  __syncthreads();

  for (int ti = 0; ti < 16; ti++){
    if (ti < 15){ issue(ti+1); CP_WAIT(1); }
    else         CP_WAIT(0);
    __syncthreads();
    const float* tile = sm + (ti & 1)*4096;

    #pragma unroll
    for (int r = 0; r < 2; r++){
      int s = wid*2 + r;
      float acc = 0.f;
      #pragma unroll
      for (int k = 0; k < 8; k++) acc = fmaf(tile[s*Hh + lane + 32*k], v_s[lane + 32*k], acc);
      acc = warp_sum(acc);
      if (!lane) tsc[s] = acc;
    }
    __syncthreads();

    float mt = tsc[0];
    #pragma unroll
    for (int s = 1; s < 16; s++) mt = fmaxf(mt, tsc[s]);
    float m_new = fmaxf(m_run, mt);
    float scale = expf(m_run - m_new);

    if (wid == 0){
      float e = (lane < 16) ? expf(tsc[lane] - m_new) : 0.f;
      if (lane < 16) wbuf[ti*16 + lane] = e;
      float es = warp_sum(e);
      if (!lane){ *red0 = es; tmaxs[ti] = m_new; }
    }
    __syncthreads();
    l_run = l_run * scale + *red0;
    m_run = m_new;

    float c = ctx_s[tid] * scale;
    #pragma unroll
    for (int s = 0; s < 16; s++) c = fmaf(wbuf[ti*16 + s], tile[s*Hh + tid], c);
    ctx_s[tid] = c;
    __syncthreads();
  }

  g_pctx[(b*NSL + slice)*Hh + tid] = ctx_s[tid];
  // unnormalized weights (rescaled in phase C)
  {
    float e = wbuf[tid] * expf(tmaxs[tid >> 4] - m_run);
    out[OFF_ATT + ((size_t)b*NST + t)*Ss + s0 + tid] = e;
  }
  if (tid == 0){
    g_pm[b*NSL + slice] = m_run;
    g_pl[b*NSL + slice] = l_run;
  }
}

// Gates GEMM + fused LSTM. 128 blocks: jt = p&15 (16 j), mt = p>>4 (32 batches).
// Bs column layout: col = gate*16 + (j - j0). Thread (tx,ty): 2 batches x 4 gates of j0+tx.
#define ASTR 36
#define BSTR 68
#define ASZ  (32*ASTR)   // 1152
#define BSZ  (32*BSTR)   // 2176
__device__ __forceinline__ void gates_lstm_phase(
    float* sm, float* fs_s, const float* __restrict__ hold, float* __restrict__ hnew)
{
  int p = blockIdx.x, tid = threadIdx.x;
  int jt = p & 15, mt = p >> 4;
  int j0 = jt * 16, m0 = mt * 32;
  float* As = sm;             // [2][32][ASTR]
  float* Bs = sm + 2*ASZ;     // [2][32][BSTR]

  // combine factors for the 32 batches (2 slices)
  if (tid < 32){
    int b = m0 + tid;
    float m0v = g_pm[b*NSL+0], m1 = g_pm[b*NSL+1];
    float Mx = fmaxf(m0v, m1);
    float f0 = expf(m0v-Mx), f1 = expf(m1-Mx);
    float L = g_pl[b*NSL+0]*f0 + g_pl[b*NSL+1]*f1;
    float inv = 1.f / L;
    fs_s[tid*2+0] = f0*inv; fs_s[tid*2+1] = f1*inv;
  }
  __syncthreads();

  auto issueB = [&](int it){
    int kt = it*32, pb = it & 1;
    #pragma unroll
    for (int i = 0; i < 2; i++){
      int idx = tid + 256*i;           // 512 cp16
      int row = idx >> 4, seg = idx & 15;
      int g = seg >> 2, q4 = (seg & 3) << 2;
      cp16(smem_u32(&Bs[pb*BSZ + row*BSTR + g*16 + q4]),
           g_WcatT + (size_t)(kt + row)*G4 + g*256 + j0 + q4);
    }
    CP_COMMIT();
  };
  auto loadA = [&](int it){
    int kt = it*32, pb = it & 1;
    int rr = tid >> 3, c4 = (tid & 7) << 2;   // 256 threads = 256 float4 exactly
    int b = m0 + rr, k = kt + c4;
    float4 a4;
    if (k < Hh){
      const float4 p0 = *(const float4*)(g_pctx + (size_t)(b*NSL)*Hh + k);
      const float4 p1 = *(const float4*)(g_pctx + (size_t)(b*NSL+1)*Hh + k);
      float f0 = fs_s[rr*2+0], f1 = fs_s[rr*2+1];
      a4.x = p0.x*f0 + p1.x*f1; a4.y = p0.y*f0 + p1.y*f1;
      a4.z = p0.z*f0 + p1.z*f1; a4.w = p0.w*f0 + p1.w*f1;
    } else {
      a4 = *(const float4*)(hold + b*Hh + (k - Hh));
    }
    As[pb*ASZ + (c4+0)*ASTR + rr] = a4.x;
    As[pb*ASZ + (c4+1)*ASTR + rr] = a4.y;
    As[pb*ASZ + (c4+2)*ASTR + rr] = a4.z;
    As[pb*ASZ + (c4+3)*ASTR + rr] = a4.w;
  };

  int tx = tid & 15, ty = tid >> 4;
  float acc[2][4] = {};

  issueB(0); loadA(0);
  for (int it = 0; it < 16; it++){
    if (it < 15){ issueB(it+1); loadA(it+1); CP_WAIT(1); }
    else          CP_WAIT(0);
    __syncthreads();
    int pb = it & 1;
    #pragma unroll
    for (int kk = 0; kk < 32; kk++){
      float2 a2 = *(const float2*)&As[pb*ASZ + kk*ASTR + ty*2];
      float b0 = Bs[pb*BSZ + kk*BSTR +      tx];
      float b1 = Bs[pb*BSZ + kk*BSTR + 16 + tx];
      float b2 = Bs[pb*BSZ + kk*BSTR + 32 + tx];
      float b3 = Bs[pb*BSZ + kk*BSTR + 48 + tx];
      acc[0][0] = fmaf(a2.x, b0, acc[0][0]); acc[1][0] = fmaf(a2.y, b0, acc[1][0]);
      acc[0][1] = fmaf(a2.x, b1, acc[0][1]); acc[1][1] = fmaf(a2.y, b1, acc[1][1]);
      acc[0][2] = fmaf(a2.x, b2, acc[0][2]); acc[1][2] = fmaf(a2.y, b2, acc[1][2]);
      acc[0][3] = fmaf(a2.x, b3, acc[0][3]); acc[1][3] = fmaf(a2.y, b3, acc[1][3]);
    }
    __syncthreads();
  }

  // fused LSTM elementwise: thread owns (2 batches) x (all 4 gates of j = j0+tx)
  int j = j0 + tx;
  #pragma unroll
  for (int i = 0; i < 2; i++){
    int b = m0 + ty*2 + i;
    float x0 = g_x[b*OUTD+0], x1 = g_x[b*OUTD+1], x2 = g_x[b*OUTD+2];
    float gv[4];
    #pragma unroll
    for (int g = 0; g < 4; g++){
      int n = g*256 + j;
      gv[g] = acc[i][g] + g_bias[n]
            + x0*g_Wx[n*OUTD+0] + x1*g_Wx[n*OUTD+1] + x2*g_Wx[n*OUTD+2];
    }
    float c  = g_c[b*Hh + j];
    float cn = sigmoidf_(gv[1])*c + sigmoidf_(gv[0])*tanhf(gv[2]);
    float hn = sigmoidf_(gv[3])*tanhf(cn);
    g_c[b*Hh + j] = cn;
    hnew[b*Hh + j] = hn;
  }
}

// v GEMM tile (32 blocks): q = 0..31: jt = q&3 (64 j), mt = q>>2 (32 batches)
__device__ __forceinline__ void v_phase(float* sm, int q, const float* __restrict__ h)
{
  int tid = threadIdx.x;
  int jt = q & 3, mt = q >> 2;
  int n0 = jt * 64, m0 = mt * 32;
  float* As = sm;
  float* Bs = sm + 2*ASZ;

  auto issueB = [&](int it){
    int kt = it*32, pb = it & 1;
    #pragma unroll
    for (int i = 0; i < 2; i++){
      int idx = tid + 256*i;
      int row = idx >> 4, c4 = (idx & 15) << 2;
      cp16(smem_u32(&Bs[pb*BSZ + row*BSTR + c4]),
           g_M + (size_t)(kt + row)*Hh + n0 + c4);
    }
    CP_COMMIT();
  };
  auto loadA = [&](int it){
    int kt = it*32, pb = it & 1;
    int rr = tid >> 3, c4 = (tid & 7) << 2;
    float4 a4 = *(const float4*)(h + (m0 + rr)*Hh + kt + c4);
    As[pb*ASZ + (c4+0)*ASTR + rr] = a4.x;
    As[pb*ASZ + (c4+1)*ASTR + rr] = a4.y;
    As[pb*ASZ + (c4+2)*ASTR + rr] = a4.z;
    As[pb*ASZ + (c4+3)*ASTR + rr] = a4.w;
  };

  int tx = tid & 15, ty = tid >> 4;
  unsigned long long acc2[2][2] = {};

  issueB(0); loadA(0);
  for (int it = 0; it < 8; it++){
    if (it < 7){ issueB(it+1); loadA(it+1); CP_WAIT(1); }
    else         CP_WAIT(0);
    __syncthreads();
    int pb = it & 1;
    #pragma unroll
    for (int kk = 0; kk < 32; kk++){
      float2 a2 = *(const float2*)&As[pb*ASZ + kk*ASTR + ty*2];
      const unsigned long long* bp = (const unsigned long long*)&Bs[pb*BSZ + kk*BSTR + tx*4];
      unsigned long long b0 = bp[0], b1 = bp[1];
      unsigned long long d0 = dup2(a2.x), d1 = dup2(a2.y);
      fma2(acc2[0][0], d0, b0); fma2(acc2[0][1], d0, b1);
      fma2(acc2[1][0], d1, b0); fma2(acc2[1][1], d1, b1);
    }
    __syncthreads();
  }

  #pragma unroll
  for (int i = 0; i < 2; i++){
    int b = m0 + ty*2 + i;
    float2 v0 = unpack2(acc2[i][0]), v1 = unpack2(acc2[i][1]);
    float av[4] = {v0.x, v0.y, v1.x, v1.y};
    #pragma unroll
    for (int jj = 0; jj < 4; jj++){
      int n = n0 + tx*4 + jj;
      g_v[b*Hh + n] = av[jj] + g_vb[n];
    }
  }
}

// pred + attention rescale (256 blocks, one per batch)
__device__ __forceinline__ void pred_phase(
    float* h_s, const float* __restrict__ h,
    const float* __restrict__ Wo, const float* __restrict__ bo,
    float* __restrict__ out, int t)
{
  int b = blockIdx.x, tid = threadIdx.x, wid = tid >> 5, lane = tid & 31;
  float fs0, fs1;
  {
    float m0v = g_pm[b*NSL+0], m1 = g_pm[b*NSL+1];
    float Mx = fmaxf(m0v, m1);
    float f0 = expf(m0v-Mx), f1 = expf(m1-Mx);
    float L = g_pl[b*NSL+0]*f0 + g_pl[b*NSL+1]*f1;
    float inv = 1.f / L;
    fs0 = f0*inv; fs1 = f1*inv;
  }
  float hn = h[b*Hh + tid];
  h_s[tid] = hn;
  if (t == NST-1) out[OFF_HID + b*Hh + tid] = hn;
  __syncthreads();

  float* att = out + OFF_ATT + ((size_t)b*NST + t)*Ss;
  att[tid]       *= fs0;
  att[tid + 256] *= fs1;

  if (wid < 3){
    float a = 0.f;
    #pragma unroll
    for (int k = lane; k < Hh; k += 32) a = fmaf(h_s[k], Wo[wid*Hh + k], a);
    a = warp_sum(a);
    if (!lane){
      float pr = a + bo[wid];
      out[OFF_PRED + ((size_t)b*NST + t)*OUTD + wid] = pr;
      g_x[b*OUTD + wid] = pr;
    }
  }
}

// ---------------------------------------------------------------- megakernel
__global__ void __launch_bounds__(NTHR, 4)
k_mega(const float* __restrict__ enc, const float* __restrict__ Wo,
       const float* __restrict__ bo, float* __restrict__ out)
{
  extern __shared__ float sm[];          // 8192 floats (32 KB)
  __shared__ float s_aux[768];           // v_s/ctx_s/wbuf | fs_s | h_s
  __shared__ float s_small[34];          // tsc[16], tmaxs[16], red0
  int p = blockIdx.x;

  // initial v from h0
  if (p >= 256 && p < 288) v_phase(sm, p - 256, g_hbuf[0]);
  gbar();

  for (int t = 0; t < NST; t++){
    const float* hold = g_hbuf[t & 1];
    float* hnew = g_hbuf[(t + 1) & 1];

    // Phase A: attention (all 512 blocks)
    attn_phase(sm, s_aux, s_aux + 256, s_aux + 512,
               s_small, s_small + 16, s_small + 32, enc, out, t);
    gbar();

    // Phase B: gates GEMM + fused LSTM (128 blocks)
    if (p < 128) gates_lstm_phase(sm, s_aux, hold, hnew);
    gbar();

    // Phase C: pred + rescale (256 blocks) || next v (32 blocks)
    if (p < 256)           pred_phase(s_aux, hnew, Wo, bo, out, t);
    else if (p < 288)      v_phase(sm, p - 256, hnew);
    gbar();
  }
}

// ---------------------------------------------------------------- launch
extern "C" void kernel_launch(void* const* d_in, const int* in_sizes, int n_in,
                              void* d_out, int out_size){
  const float* enc  = (const float*)d_in[0];
  const float* ehid = (const float*)d_in[1];
  const float* ecell= (const float*)d_in[2];
  const float* Wa   = (const float*)d_in[3];
  const float* ba   = (const float*)d_in[4];
  const float* Ua   = (const float*)d_in[5];
  /* d_in[6] (bua): softmax-invariant, unused */
  const float* Wih  = (const float*)d_in[7];
  const float* Whh  = (const float*)d_in[8];
  const float* bih  = (const float*)d_in[9];
  const float* bhh  = (const float*)d_in[10];
  const float* Wo   = (const float*)d_in[11];
  const float* bo   = (const float*)d_in[12];
  float* out = (float*)d_out;

  k_init<<<256, 256>>>(ehid, ecell);
  k_pack<<<G4, 512>>>(Wih, Whh, bih, bhh);
  k_prep<<<Hh + 1, 256>>>(Wa, ba, Ua);
  k_mega<<<GRID, NTHR, 32768>>>(enc, Wo, bo, out);
}

// round 9
// speedup vs baseline: 1.2061x; 1.2061x over previous
#include <cuda_runtime.h>
#include <math.h>
#include <stdint.h>

// Problem dims
#define Bb   256
#define Ss   512
#define Hh   256
#define OUTD 3
#define NST  64
#define INW  259
#define G4   (4*Hh)
#define NSLICE 4
#define SLROWS (Ss/NSLICE)   // 128

// Output layout
#define OFF_PRED 0
#define OFF_HID  (Bb*NST*OUTD)          // 49152
#define OFF_ATT  (OFF_HID + Bb*Hh)      // 114688

// Persistent device state
__device__ float g_hbuf[2][Bb*Hh];
__device__ float g_c[Bb*Hh];
__device__ float g_x[Bb*OUTD];
__device__ float g_v[Bb*Hh];
__device__ float g_WcatT[512*G4];  // [k][n]
__device__ float g_Wx[G4*OUTD];
__device__ float g_bias[G4];
__device__ float g_M[Hh*Hh];       // [k][j]
__device__ float g_vb[Hh];
__device__ float g_pm[Bb*NSLICE];
__device__ float g_pl[Bb*NSLICE];
__device__ float g_pctx[Bb*NSLICE*Hh];

__device__ __forceinline__ float warp_sum(float v){
  #pragma unroll
  for (int o = 16; o; o >>= 1) v += __shfl_xor_sync(0xffffffffu, v, o);
  return v;
}
__device__ __forceinline__ float sigmoidf_(float x){ return 1.f/(1.f+expf(-x)); }

__device__ __forceinline__ uint32_t smem_u32(const void* p){
  return (uint32_t)__cvta_generic_to_shared(p);
}
__device__ __forceinline__ void cp16(uint32_t dst, const void* src){
  asm volatile("cp.async.cg.shared.global [%0], [%1], 16;" :: "r"(dst), "l"(src));
}
#define CP_COMMIT() asm volatile("cp.async.commit_group;")
#define CP_WAIT(n)  asm volatile("cp.async.wait_group %0;" :: "n"(n))

__device__ __forceinline__ void fma2(unsigned long long &d, unsigned long long a, unsigned long long b){
  asm("fma.rn.f32x2 %0, %1, %2, %3;" : "=l"(d) : "l"(a), "l"(b), "l"(d));
}
__device__ __forceinline__ unsigned long long dup2(float v){
  unsigned long long r; uint32_t u = __float_as_uint(v);
  asm("mov.b64 %0, {%1, %1};" : "=l"(r) : "r"(u));
  return r;
}
__device__ __forceinline__ float2 unpack2(unsigned long long v){
  uint32_t lo, hi;
  asm("mov.b64 {%0, %1}, %2;" : "=r"(lo), "=r"(hi) : "l"(v));
  return make_float2(__uint_as_float(lo), __uint_as_float(hi));
}

// ---------------------------------------------------------------- init/pack/prep
__global__ void k_init(const float* __restrict__ eh, const float* __restrict__ ec){
  int i = blockIdx.x*blockDim.x + threadIdx.x;
  if (i < Bb*Hh){ g_hbuf[0][i] = eh[i]; g_c[i] = ec[i]; }
  if (i < Bb*OUTD) g_x[i] = 0.f;
}

__global__ void k_pack(const float* __restrict__ Wih, const float* __restrict__ Whh,
                       const float* __restrict__ bih, const float* __restrict__ bhh){
  int j = blockIdx.x, k = threadIdx.x;
  float val = (k < Hh) ? Wih[j*INW + OUTD + k] : Whh[j*Hh + (k - Hh)];
  g_WcatT[(size_t)k*G4 + j] = val;
  if (k < OUTD) g_Wx[j*OUTD + k] = Wih[j*INW + k];
  if (k == 0)   g_bias[j] = bih[j] + bhh[j];
}

__global__ void k_prep(const float* __restrict__ Wa, const float* __restrict__ ba,
                       const float* __restrict__ Ua){
  int kk = blockIdx.x, j = threadIdx.x;
  float a = 0.f;
  if (kk < Hh){
    #pragma unroll 4
    for (int g = 0; g < Hh; g++) a = fmaf(Wa[g*Hh + kk], Ua[g*Hh + j], a);
    g_M[kk*Hh + j] = a;
  } else {
    #pragma unroll 4
    for (int g = 0; g < Hh; g++) a = fmaf(ba[g], Ua[g*Hh + j], a);
    g_vb[j] = a;
  }
}

// ---------------------------------------------------------------- attention (R6 config: 4 slices, 2-stage ring)
#define TR 16
__global__ void k_attn(const float* __restrict__ enc, float* __restrict__ out, int t){
  __shared__ float buf[2][TR][Hh];    // 32 KB
  __shared__ float v_s[Hh];
  __shared__ float ctx_s[Hh];
  __shared__ float tsc[TR];
  __shared__ float wbuf[SLROWS];
  __shared__ float tmaxs[8];
  __shared__ float red0;
  int slice = blockIdx.x, b = blockIdx.y;
  int tid = threadIdx.x, wid = tid >> 5, lane = tid & 31;
  int s0 = slice * SLROWS;
  const float* encb = enc + (size_t)b*Ss*Hh;

  {
    const float4* src = (const float4*)(encb + (size_t)s0*Hh);
    uint32_t dst = smem_u32(&buf[0][0][0]);
    #pragma unroll
    for (int i = 0; i < 4; i++){
      int idx = tid + 256*i;
      cp16(dst + idx*16, src + idx);
    }
    CP_COMMIT();
  }
  v_s[tid] = g_v[b*Hh + tid];
  ctx_s[tid] = 0.f;
  float m_run = -3.0e38f, l_run = 0.f;
  __syncthreads();

  for (int ti = 0; ti < 8; ti++){
    if (ti < 7){
      const float4* src = (const float4*)(encb + (size_t)(s0 + (ti+1)*TR)*Hh);
      uint32_t dst = smem_u32(&buf[(ti+1)&1][0][0]);
      #pragma unroll
      for (int i = 0; i < 4; i++){
        int idx = tid + 256*i;
        cp16(dst + idx*16, src + idx);
      }
      CP_COMMIT();
      CP_WAIT(1);
    } else {
      CP_WAIT(0);
    }
    __syncthreads();
    float (*tile)[Hh] = buf[ti&1];

    #pragma unroll
    for (int r = 0; r < 2; r++){
      int s = wid*2 + r;
      float acc = 0.f;
      #pragma unroll
      for (int k = 0; k < 8; k++) acc = fmaf(tile[s][lane + 32*k], v_s[lane + 32*k], acc);
      acc = warp_sum(acc);
      if (!lane) tsc[s] = acc;
    }
    __syncthreads();

    float mt = tsc[0];
    #pragma unroll
    for (int s = 1; s < TR; s++) mt = fmaxf(mt, tsc[s]);
    float m_new = fmaxf(m_run, mt);
    float scale = expf(m_run - m_new);

    if (wid == 0){
      float e = (lane < TR) ? expf(tsc[lane] - m_new) : 0.f;
      if (lane < TR) wbuf[ti*TR + lane] = e;
      float es = warp_sum(e);
      if (!lane){ red0 = es; tmaxs[ti] = m_new; }
    }
    __syncthreads();
    l_run = l_run * scale + red0;
    m_run = m_new;

    float c = ctx_s[tid] * scale;
    #pragma unroll
    for (int s = 0; s < TR; s++) c = fmaf(wbuf[ti*TR + s], tile[s][tid], c);
    ctx_s[tid] = c;
    __syncthreads();
  }

  g_pctx[(b*NSLICE + slice)*Hh + tid] = ctx_s[tid];
  if (tid < SLROWS){
    float e = wbuf[tid] * expf(tmaxs[tid >> 4] - m_run);
    out[OFF_ATT + ((size_t)b*NST + t)*Ss + s0 + tid] = e;  // rescaled in k_post
  }
  if (tid == 0){
    g_pm[b*NSLICE + slice] = m_run;
    g_pl[b*NSLICE + slice] = l_run;
  }
}

// ---------------------------------------------------------------- gates GEMM + fused LSTM
// 128 blocks x 256 threads: jt = p&15 (16 j's), mt = p>>4 (32 batches).
// Bs col layout: gate*16 + (j-j0). Thread (tx,ty): 2 batches x 4 gates of j0+tx.
#define ASTR 36
#define BSTR 68
#define ASZ  (32*ASTR)
#define BSZ  (32*BSTR)
__global__ void __launch_bounds__(256)
k_gl(const float* __restrict__ hold, float* __restrict__ hnew){
  __shared__ float As[2][ASZ];
  __shared__ float Bs[2][BSZ];
  __shared__ float fs_s[32][4];
  int p = blockIdx.x, tid = threadIdx.x;
  int jt = p & 15, mt = p >> 4;
  int j0 = jt * 16, m0 = mt * 32;

  if (tid < 32){
    int b = m0 + tid;
    float m0v = g_pm[b*4+0], m1 = g_pm[b*4+1], m2 = g_pm[b*4+2], m3 = g_pm[b*4+3];
    float Mx = fmaxf(fmaxf(m0v, m1), fmaxf(m2, m3));
    float f0 = expf(m0v-Mx), f1 = expf(m1-Mx), f2 = expf(m2-Mx), f3 = expf(m3-Mx);
    float L = g_pl[b*4+0]*f0 + g_pl[b*4+1]*f1 + g_pl[b*4+2]*f2 + g_pl[b*4+3]*f3;
    float inv = 1.f / L;
    fs_s[tid][0] = f0*inv; fs_s[tid][1] = f1*inv;
    fs_s[tid][2] = f2*inv; fs_s[tid][3] = f3*inv;
  }
  __syncthreads();

  auto issueB = [&](int it){
    int kt = it*32, pb = it & 1;
    #pragma unroll
    for (int i = 0; i < 2; i++){
      int idx = tid + 256*i;            // 512 cp16
      int row = idx >> 4, seg = idx & 15;
      int g = seg >> 2, q4 = (seg & 3) << 2;
      cp16(smem_u32(&Bs[pb][row*BSTR + g*16 + q4]),
           g_WcatT + (size_t)(kt + row)*G4 + g*256 + j0 + q4);
    }
    CP_COMMIT();
  };
  auto loadA = [&](int it){
    int kt = it*32, pb = it & 1;
    int rr = tid >> 3, c4 = (tid & 7) << 2;
    int b = m0 + rr, k = kt + c4;
    float4 a4;
    if (k < Hh){
      const float* pp = g_pctx + (size_t)(b*NSLICE)*Hh + k;
      float4 p0 = *(const float4*)(pp);
      float4 p1 = *(const float4*)(pp + Hh);
      float4 p2 = *(const float4*)(pp + 2*Hh);
      float4 p3 = *(const float4*)(pp + 3*Hh);
      float f0 = fs_s[rr][0], f1 = fs_s[rr][1], f2 = fs_s[rr][2], f3 = fs_s[rr][3];
      a4.x = p0.x*f0 + p1.x*f1 + p2.x*f2 + p3.x*f3;
      a4.y = p0.y*f0 + p1.y*f1 + p2.y*f2 + p3.y*f3;
      a4.z = p0.z*f0 + p1.z*f1 + p2.z*f2 + p3.z*f3;
      a4.w = p0.w*f0 + p1.w*f1 + p2.w*f2 + p3.w*f3;
    } else {
      a4 = *(const float4*)(hold + b*Hh + (k - Hh));
    }
    As[pb][(c4+0)*ASTR + rr] = a4.x;
    As[pb][(c4+1)*ASTR + rr] = a4.y;
    As[pb][(c4+2)*ASTR + rr] = a4.z;
    As[pb][(c4+3)*ASTR + rr] = a4.w;
  };

  int tx = tid & 15, ty = tid >> 4;
  float acc[2][4] = {};

  issueB(0); loadA(0);
  for (int it = 0; it < 16; it++){
    if (it < 15){ issueB(it+1); loadA(it+1); CP_WAIT(1); }
    else          CP_WAIT(0);
    __syncthreads();
    int pb = it & 1;
    #pragma unroll
    for (int kk = 0; kk < 32; kk++){
      float2 a2 = *(const float2*)&As[pb][kk*ASTR + ty*2];
      float b0 = Bs[pb][kk*BSTR +      tx];
      float b1 = Bs[pb][kk*BSTR + 16 + tx];
      float b2 = Bs[pb][kk*BSTR + 32 + tx];
      float b3 = Bs[pb][kk*BSTR + 48 + tx];
      acc[0][0] = fmaf(a2.x, b0, acc[0][0]); acc[1][0] = fmaf(a2.y, b0, acc[1][0]);
      acc[0][1] = fmaf(a2.x, b1, acc[0][1]); acc[1][1] = fmaf(a2.y, b1, acc[1][1]);
      acc[0][2] = fmaf(a2.x, b2, acc[0][2]); acc[1][2] = fmaf(a2.y, b2, acc[1][2]);
      acc[0][3] = fmaf(a2.x, b3, acc[0][3]); acc[1][3] = fmaf(a2.y, b3, acc[1][3]);
    }
    __syncthreads();
  }

  int j = j0 + tx;
  #pragma unroll
  for (int i = 0; i < 2; i++){
    int b = m0 + ty*2 + i;
    float x0 = g_x[b*OUTD+0], x1 = g_x[b*OUTD+1], x2 = g_x[b*OUTD+2];
    float gv[4];
    #pragma unroll
    for (int g = 0; g < 4; g++){
      int n = g*256 + j;
      gv[g] = acc[i][g] + g_bias[n]
            + x0*g_Wx[n*OUTD+0] + x1*g_Wx[n*OUTD+1] + x2*g_Wx[n*OUTD+2];
    }
    float c  = g_c[b*Hh + j];
    float cn = sigmoidf_(gv[1])*c + sigmoidf_(gv[0])*tanhf(gv[2]);
    float hn = sigmoidf_(gv[3])*tanhf(cn);
    g_c[b*Hh + j] = cn;
    hnew[b*Hh + j] = hn;
  }
}

// ---------------------------------------------------------------- post: pred+rescale (256) || v GEMM (32)
__global__ void __launch_bounds__(256)
k_post(const float* __restrict__ h, const float* __restrict__ Wo,
       const float* __restrict__ bo, float* __restrict__ out, int t, int writeHid){
  __shared__ float sm[2*ASZ + 2*BSZ];   // v tiles; pred reuses front as h_s
  int p = blockIdx.x, tid = threadIdx.x;

  if (p < 256){
    int b = p, wid = tid >> 5, lane = tid & 31;
    float* h_s = sm;
    float fs[4];
    {
      float m0v = g_pm[b*4+0], m1 = g_pm[b*4+1], m2 = g_pm[b*4+2], m3 = g_pm[b*4+3];
      float Mx = fmaxf(fmaxf(m0v, m1), fmaxf(m2, m3));
      float f0 = expf(m0v-Mx), f1 = expf(m1-Mx), f2 = expf(m2-Mx), f3 = expf(m3-Mx);
      float L = g_pl[b*4+0]*f0 + g_pl[b*4+1]*f1 + g_pl[b*4+2]*f2 + g_pl[b*4+3]*f3;
      float inv = 1.f / L;
      fs[0] = f0*inv; fs[1] = f1*inv; fs[2] = f2*inv; fs[3] = f3*inv;
    }
    float hn = h[b*Hh + tid];
    h_s[tid] = hn;
    if (writeHid) out[OFF_HID + b*Hh + tid] = hn;
    __syncthreads();

    float* att = out + OFF_ATT + ((size_t)b*NST + t)*Ss;
    att[tid]       *= fs[tid >> 7];
    att[tid + 256] *= fs[(tid + 256) >> 7];

    if (wid < 3){
      float a = 0.f;
      #pragma unroll
      for (int k = lane; k < Hh; k += 32) a = fmaf(h_s[k], Wo[wid*Hh + k], a);
      a = warp_sum(a);
      if (!lane){
        float pr = a + bo[wid];
        out[OFF_PRED + ((size_t)b*NST + t)*OUTD + wid] = pr;
        g_x[b*OUTD + wid] = pr;
      }
    }
  } else {
    // v tile: q = p-256 in 0..31; jt = q&3 (64 j), mt = q>>2 (32 batches)
    int q = p - 256;
    int jt = q & 3, mt = q >> 2;
    int n0 = jt * 64, m0 = mt * 32;
    float* As = sm;
    float* Bs = sm + 2*ASZ;

    auto issueB = [&](int it){
      int kt = it*32, pb = it & 1;
      #pragma unroll
      for (int i = 0; i < 2; i++){
        int idx = tid + 256*i;
        int row = idx >> 4, c4 = (idx & 15) << 2;
        cp16(smem_u32(&Bs[pb*BSZ + row*BSTR + c4]),
             g_M + (size_t)(kt + row)*Hh + n0 + c4);
      }
      CP_COMMIT();
    };
    auto loadA = [&](int it){
      int kt = it*32, pb = it & 1;
      int rr = tid >> 3, c4 = (tid & 7) << 2;
      float4 a4 = *(const float4*)(h + (m0 + rr)*Hh + kt + c4);
      As[pb*ASZ + (c4+0)*ASTR + rr] = a4.x;
      As[pb*ASZ + (c4+1)*ASTR + rr] = a4.y;
      As[pb*ASZ + (c4+2)*ASTR + rr] = a4.z;
      As[pb*ASZ + (c4+3)*ASTR + rr] = a4.w;
    };

    int tx = tid & 15, ty = tid >> 4;
    unsigned long long acc2[2][2] = {};

    issueB(0); loadA(0);
    for (int it = 0; it < 8; it++){
      if (it < 7){ issueB(it+1); loadA(it+1); CP_WAIT(1); }
      else         CP_WAIT(0);
      __syncthreads();
      int pb = it & 1;
      #pragma unroll
      for (int kk = 0; kk < 32; kk++){
        float2 a2 = *(const float2*)&As[pb*ASZ + kk*ASTR + ty*2];
        const unsigned long long* bp = (const unsigned long long*)&Bs[pb*BSZ + kk*BSTR + tx*4];
        unsigned long long b0 = bp[0], b1 = bp[1];
        unsigned long long d0 = dup2(a2.x), d1 = dup2(a2.y);
        fma2(acc2[0][0], d0, b0); fma2(acc2[0][1], d0, b1);
        fma2(acc2[1][0], d1, b0); fma2(acc2[1][1], d1, b1);
      }
      __syncthreads();
    }

    #pragma unroll
    for (int i = 0; i < 2; i++){
      int b = m0 + ty*2 + i;
      float2 v0 = unpack2(acc2[i][0]), v1 = unpack2(acc2[i][1]);
      float av[4] = {v0.x, v0.y, v1.x, v1.y};
      #pragma unroll
      for (int jj = 0; jj < 4; jj++){
        int n = n0 + tx*4 + jj;
        g_v[b*Hh + n] = av[jj] + g_vb[n];
      }
    }
  }
}

// initial v from h0 (32 blocks)
__global__ void __launch_bounds__(256)
k_vinit(const float* __restrict__ h){
  __shared__ float sm[2*ASZ + 2*BSZ];
  int q = blockIdx.x, tid = threadIdx.x;
  int jt = q & 3, mt = q >> 2;
  int n0 = jt * 64, m0 = mt * 32;
  float* As = sm;
  float* Bs = sm + 2*ASZ;

  auto issueB = [&](int it){
    int kt = it*32, pb = it & 1;
    #pragma unroll
    for (int i = 0; i < 2; i++){
      int idx = tid + 256*i;
      int row = idx >> 4, c4 = (idx & 15) << 2;
      cp16(smem_u32(&Bs[pb*BSZ + row*BSTR + c4]),
           g_M + (size_t)(kt + row)*Hh + n0 + c4);
    }
    CP_COMMIT();
  };
  auto loadA = [&](int it){
    int kt = it*32, pb = it & 1;
    int rr = tid >> 3, c4 = (tid & 7) << 2;
    float4 a4 = *(const float4*)(h + (m0 + rr)*Hh + kt + c4);
    As[pb*ASZ + (c4+0)*ASTR + rr] = a4.x;
    As[pb*ASZ + (c4+1)*ASTR + rr] = a4.y;
    As[pb*ASZ + (c4+2)*ASTR + rr] = a4.z;
    As[pb*ASZ + (c4+3)*ASTR + rr] = a4.w;
  };

  int tx = tid & 15, ty = tid >> 4;
  unsigned long long acc2[2][2] = {};
  issueB(0); loadA(0);
  for (int it = 0; it < 8; it++){
    if (it < 7){ issueB(it+1); loadA(it+1); CP_WAIT(1); }
    else         CP_WAIT(0);
    __syncthreads();
    int pb = it & 1;
    #pragma unroll
    for (int kk = 0; kk < 32; kk++){
      float2 a2 = *(const float2*)&As[pb*ASZ + kk*ASTR + ty*2];
      const unsigned long long* bp = (const unsigned long long*)&Bs[pb*BSZ + kk*BSTR + tx*4];
      unsigned long long b0 = bp[0], b1 = bp[1];
      unsigned long long d0 = dup2(a2.x), d1 = dup2(a2.y);
      fma2(acc2[0][0], d0, b0); fma2(acc2[0][1], d0, b1);
      fma2(acc2[1][0], d1, b0); fma2(acc2[1][1], d1, b1);
    }
    __syncthreads();
  }
  #pragma unroll
  for (int i = 0; i < 2; i++){
    int b = m0 + ty*2 + i;
    float2 v0 = unpack2(acc2[i][0]), v1 = unpack2(acc2[i][1]);
    float av[4] = {v0.x, v0.y, v1.x, v1.y};
    #pragma unroll
    for (int jj = 0; jj < 4; jj++){
      int n = n0 + tx*4 + jj;
      g_v[b*Hh + n] = av[jj] + g_vb[n];
    }
  }
}

// ---------------------------------------------------------------- launch
extern "C" void kernel_launch(void* const* d_in, const int* in_sizes, int n_in,
                              void* d_out, int out_size){
  const float* enc  = (const float*)d_in[0];
  const float* ehid = (const float*)d_in[1];
  const float* ecell= (const float*)d_in[2];
  const float* Wa   = (const float*)d_in[3];
  const float* ba   = (const float*)d_in[4];
  const float* Ua   = (const float*)d_in[5];
  /* d_in[6] (bua): softmax-invariant, unused */
  const float* Wih  = (const float*)d_in[7];
  const float* Whh  = (const float*)d_in[8];
  const float* bih  = (const float*)d_in[9];
  const float* bhh  = (const float*)d_in[10];
  const float* Wo   = (const float*)d_in[11];
  const float* bo   = (const float*)d_in[12];
  float* out = (float*)d_out;

  // resolve device-global addresses for ping-pong h
  float* hb0; cudaGetSymbolAddress((void**)&hb0, g_hbuf);
  float* hb1 = hb0 + Bb*Hh;

  k_init<<<256, 256>>>(ehid, ecell);
  k_pack<<<G4, 512>>>(Wih, Whh, bih, bhh);
  k_prep<<<Hh + 1, 256>>>(Wa, ba, Ua);
  k_vinit<<<32, 256>>>(hb0);
  for (int t = 0; t < NST; t++){
    const float* hold = (t & 1) ? hb1 : hb0;
    float* hnew       = (t & 1) ? hb0 : hb1;
    k_attn<<<dim3(NSLICE, Bb), 256>>>(enc, out, t);
    k_gl<<<128, 256>>>(hold, hnew);
    k_post<<<288, 256>>>(hnew, Wo, bo, out, t, t == NST-1);
  }
}